// round 15
// baseline (speedup 1.0000x reference)
#include <cuda_runtime.h>
#include <cuda_bf16.h>
#include <math.h>

#define TS   1024
#define BS   64
#define HID  512
#define G4   2048
#define NCTA 128
#define LTHREADS 512
#define MROWS 65536
#define TBH  ((size_t)TS * BS * HID)
#define BH   (BS * HID)

// ---- lstm smem ----
#define WJ_STRIDE 2052
#define WG_STRIDE 512
#define P_OFF     (8 * WJ_STRIDE)
#define SEG_F4    88
#define BH_F4     44
#define P_FLOATS  (32 * SEG_F4 * 4)
#define LSTM_SMEM ((P_OFF + P_FLOATS) * 4)

// ---- mma gemm smem (bf16 units / bytes) ----
#define AS_STRIDE 72
#define GS_AHI    0
#define GS_ALO    18432
#define GS_BHI    36864
#define GS_BLO    55296
#define GS_BIAS   73728
#define GSMEM     (73728 + 512)
#define DS_STRIDE 132

// Scratch (device globals)
__device__ float g_xgates[(size_t)G4 * MROWS];     // transposed [col][row]
__device__ float g_out1[(size_t)TS * BS * HID];
__device__ float g_hbufT[2][HID * BS];             // transposed h: [k][b]
__device__ unsigned int g_flagsB[2][64];           // per-(group, jb) step flags
__device__ __nv_bfloat16 g_xhi[(size_t)MROWS * HID];
__device__ __nv_bfloat16 g_xlo[(size_t)MROWS * HID];
__device__ __nv_bfloat16 g_whi[(size_t)G4 * HID];
__device__ __nv_bfloat16 g_wlo[(size_t)G4 * HID];

// ---- packed f32x2 helpers ----
__device__ __forceinline__ unsigned long long fma2(unsigned long long a,
                                                   unsigned long long b,
                                                   unsigned long long c) {
    unsigned long long d;
    asm("fma.rn.f32x2 %0, %1, %2, %3;" : "=l"(d) : "l"(a), "l"(b), "l"(c));
    return d;
}
__device__ __forceinline__ unsigned long long pack2(float x, float y) {
    unsigned long long d;
    asm("mov.b64 %0, {%1, %2};" : "=l"(d) : "f"(x), "f"(y));
    return d;
}
__device__ __forceinline__ float2 unpack2(unsigned long long v) {
    float2 r;
    asm("mov.b64 {%0, %1}, %2;" : "=f"(r.x), "=f"(r.y) : "l"(v));
    return r;
}
__device__ __forceinline__ void st_release(unsigned int* p, unsigned int v) {
    asm volatile("st.release.gpu.global.u32 [%0], %1;" :: "l"(p), "r"(v) : "memory");
}
__device__ __forceinline__ unsigned int ld_acquire(const unsigned int* p) {
    unsigned int v;
    asm volatile("ld.acquire.gpu.global.u32 %0, [%1];" : "=r"(v) : "l"(p) : "memory");
    return v;
}
// fast activations (MUFU-based; error ~1e-6 vs 1e-3 budget, validated R13/R14)
__device__ __forceinline__ float fsigmoid_(float x) {
    return __fdividef(1.f, 1.f + __expf(-x));
}
__device__ __forceinline__ float ftanh_(float x) {
    return 1.f - __fdividef(2.f, 1.f + __expf(2.f * x));
}

__device__ __forceinline__ void mma16816(float* d, const unsigned* a, const unsigned* b) {
    asm volatile(
        "mma.sync.aligned.m16n8k16.row.col.f32.bf16.bf16.f32 "
        "{%0,%1,%2,%3}, {%4,%5,%6,%7}, {%8,%9}, {%0,%1,%2,%3};"
        : "+f"(d[0]), "+f"(d[1]), "+f"(d[2]), "+f"(d[3])
        : "r"(a[0]), "r"(a[1]), "r"(a[2]), "r"(a[3]), "r"(b[0]), "r"(b[1]));
}

// ---------------------------------------------------------------------------
// Split-convert fp32 -> bf16 hi/lo. Optionally resets recurrence flags.
// ---------------------------------------------------------------------------
__global__ void convert_split(const float* __restrict__ src,
                              __nv_bfloat16* __restrict__ hi,
                              __nv_bfloat16* __restrict__ lo,
                              size_t n, int reset)
{
    if (reset && blockIdx.x == 0 && threadIdx.x < 128)
        ((unsigned int*)g_flagsB)[threadIdx.x] = 0u;
    size_t stride = (size_t)gridDim.x * blockDim.x;
    for (size_t i = (size_t)blockIdx.x * blockDim.x + threadIdx.x; i < n; i += stride) {
        float v = src[i];
        __nv_bfloat16 h = __float2bfloat16(v);
        hi[i] = h;
        lo[i] = __float2bfloat16(v - __bfloat162float(h));
    }
}

// ---------------------------------------------------------------------------
// bf16-split projection GEMM via mma.sync, k-block register-prefetch pipeline.
// (verified round-12 version, unchanged)
// ---------------------------------------------------------------------------
__global__ __launch_bounds__(512, 1) void gemm_mma(
    const __nv_bfloat16* __restrict__ Ahi, const __nv_bfloat16* __restrict__ Alo,
    const __nv_bfloat16* __restrict__ Bhi, const __nv_bfloat16* __restrict__ Blo,
    const float* __restrict__ b1, const float* __restrict__ b2)
{
    extern __shared__ char smem[];
    __nv_bfloat16* As_hi = (__nv_bfloat16*)(smem + GS_AHI);
    __nv_bfloat16* As_lo = (__nv_bfloat16*)(smem + GS_ALO);
    __nv_bfloat16* Bs_hi = (__nv_bfloat16*)(smem + GS_BHI);
    __nv_bfloat16* Bs_lo = (__nv_bfloat16*)(smem + GS_BLO);
    float* bias_sm = (float*)(smem + GS_BIAS);
    float* Ds = (float*)smem;

    const int tid  = threadIdx.x;
    const int warp = tid >> 5;
    const int lane = tid & 31;
    const int wm = (warp & 3) * 32;
    const int wn = (warp >> 2) * 32;
    const int g0 = blockIdx.x * 128;
    const int m0 = blockIdx.y * 128;

    for (int i = tid; i < 128; i += 512)
        bias_sm[i] = b1[g0 + i] + b2[g0 + i];

    float d[2][4][4];
#pragma unroll
    for (int fi = 0; fi < 2; fi++)
#pragma unroll
        for (int fj = 0; fj < 4; fj++)
#pragma unroll
            for (int r = 0; r < 4; r++) d[fi][fj][r] = 0.f;

    const int lr = lane >> 2;
    const int lc = lane & 3;

    const int row0 = tid >> 3,        c0 = tid & 7;
    const int row1 = (tid + 512) >> 3, c1 = (tid + 512) & 7;
    const size_t a0base = (size_t)(m0 + row0) * HID + c0 * 8;
    const size_t a1base = (size_t)(m0 + row1) * HID + c1 * 8;
    const size_t b0base = (size_t)(g0 + row0) * HID + c0 * 8;
    const size_t b1base = (size_t)(g0 + row1) * HID + c1 * 8;
    const int d0 = row0 * AS_STRIDE + c0 * 8;
    const int d1 = row1 * AS_STRIDE + c1 * 8;

    float4 rah0, rah1, ral0, ral1, rbh0, rbh1, rbl0, rbl1;
    {
        rah0 = *(const float4*)(Ahi + a0base); rah1 = *(const float4*)(Ahi + a1base);
        ral0 = *(const float4*)(Alo + a0base); ral1 = *(const float4*)(Alo + a1base);
        rbh0 = *(const float4*)(Bhi + b0base); rbh1 = *(const float4*)(Bhi + b1base);
        rbl0 = *(const float4*)(Blo + b0base); rbl1 = *(const float4*)(Blo + b1base);
    }

    for (int kb = 0; kb < 8; kb++) {
        __syncthreads();
        *(float4*)(As_hi + d0) = rah0; *(float4*)(As_hi + d1) = rah1;
        *(float4*)(As_lo + d0) = ral0; *(float4*)(As_lo + d1) = ral1;
        *(float4*)(Bs_hi + d0) = rbh0; *(float4*)(Bs_hi + d1) = rbh1;
        *(float4*)(Bs_lo + d0) = rbl0; *(float4*)(Bs_lo + d1) = rbl1;
        __syncthreads();

        if (kb < 7) {
            const int k0 = (kb + 1) * 64;
            rah0 = *(const float4*)(Ahi + a0base + k0); rah1 = *(const float4*)(Ahi + a1base + k0);
            ral0 = *(const float4*)(Alo + a0base + k0); ral1 = *(const float4*)(Alo + a1base + k0);
            rbh0 = *(const float4*)(Bhi + b0base + k0); rbh1 = *(const float4*)(Bhi + b1base + k0);
            rbl0 = *(const float4*)(Blo + b0base + k0); rbl1 = *(const float4*)(Blo + b1base + k0);
        }

#pragma unroll
        for (int ks = 0; ks < 4; ks++) {
            const int kc = ks * 16 + lc * 2;
            unsigned ah[2][4], al[2][4];
#pragma unroll
            for (int fi = 0; fi < 2; fi++) {
                int base = (wm + fi * 16 + lr) * AS_STRIDE;
                ah[fi][0] = *(const unsigned*)(As_hi + base + kc);
                ah[fi][1] = *(const unsigned*)(As_hi + base + 8 * AS_STRIDE + kc);
                ah[fi][2] = *(const unsigned*)(As_hi + base + kc + 8);
                ah[fi][3] = *(const unsigned*)(As_hi + base + 8 * AS_STRIDE + kc + 8);
                al[fi][0] = *(const unsigned*)(As_lo + base + kc);
                al[fi][1] = *(const unsigned*)(As_lo + base + 8 * AS_STRIDE + kc);
                al[fi][2] = *(const unsigned*)(As_lo + base + kc + 8);
                al[fi][3] = *(const unsigned*)(As_lo + base + 8 * AS_STRIDE + kc + 8);
            }
            unsigned bh[4][2], bl[4][2];
#pragma unroll
            for (int fj = 0; fj < 4; fj++) {
                int base = (wn + fj * 8 + lr) * AS_STRIDE;
                bh[fj][0] = *(const unsigned*)(Bs_hi + base + kc);
                bh[fj][1] = *(const unsigned*)(Bs_hi + base + kc + 8);
                bl[fj][0] = *(const unsigned*)(Bs_lo + base + kc);
                bl[fj][1] = *(const unsigned*)(Bs_lo + base + kc + 8);
            }
#pragma unroll
            for (int fi = 0; fi < 2; fi++)
#pragma unroll
                for (int fj = 0; fj < 4; fj++) {
                    mma16816(d[fi][fj], ah[fi], bh[fj]);
                    mma16816(d[fi][fj], ah[fi], bl[fj]);
                    mma16816(d[fi][fj], al[fi], bh[fj]);
                }
        }
    }

    __syncthreads();
#pragma unroll
    for (int fi = 0; fi < 2; fi++)
#pragma unroll
        for (int fj = 0; fj < 4; fj++) {
            int r = wm + fi * 16 + lr;
            int c = wn + fj * 8 + lc * 2;
            Ds[(c + 0) * DS_STRIDE + r]     = d[fi][fj][0];
            Ds[(c + 1) * DS_STRIDE + r]     = d[fi][fj][1];
            Ds[(c + 0) * DS_STRIDE + r + 8] = d[fi][fj][2];
            Ds[(c + 1) * DS_STRIDE + r + 8] = d[fi][fj][3];
        }
    __syncthreads();
#pragma unroll
    for (int idx = tid; idx < 128 * 32; idx += 512) {
        int col = idx >> 5, ch = idx & 31;
        float4 v = *(const float4*)(Ds + col * DS_STRIDE + ch * 4);
        float b = bias_sm[col];
        v.x += b; v.y += b; v.z += b; v.w += b;
        *(float4*)(g_xgates + (size_t)(g0 + col) * MROWS + m0 + ch * 4) = v;
    }
}

// ---------------------------------------------------------------------------
// Persistent recurrence — R14 structure, but the barrier's serialized atomic
// chain is replaced by: per-CTA OWN flag st.release (64 distinct addresses,
// 2 cache lines) + warp-0 lane-parallel poll of all 64 flags + syncthreads.
// One arrival + one polling warp per CTA (R11/R13 contention lessons kept).
// ---------------------------------------------------------------------------
__global__ __launch_bounds__(LTHREADS, 1) void lstm_kernel(
    const float* __restrict__ Whh, const float* __restrict__ h0,
    const float* __restrict__ c0, const float* __restrict__ xg,
    float* __restrict__ out, float* __restrict__ hn, float* __restrict__ cn)
{
    extern __shared__ float sm[];
    float* w_sm = sm;
    float* p_sm = sm + P_OFF;

    const int tid  = threadIdx.x;
    const int cta  = blockIdx.x;
    const int jb   = cta & 63;
    const int bb   = cta >> 6;
    const int warp = tid >> 5;
    const int lane = tid & 31;
    const int bh = warp & 1;
    const int kq = warp >> 1;
    const int bq = lane & 3;
    const int jl = lane >> 2;
    const int k0b = kq * 64;
    const int cj = warp;
    const int cb = lane;

    {
        const float4* Wsrc = (const float4*)Whh;
#pragma unroll
        for (int idx = tid; idx < 4096; idx += LTHREADS) {
            int wj = idx >> 9, g = (idx >> 7) & 3, k4 = idx & 127;
            *(float4*)&w_sm[wj * WJ_STRIDE + g * WG_STRIDE + k4 * 4] =
                Wsrc[(((size_t)(g * HID + jb * 8 + wj)) * HID >> 2) + k4];
        }
    }

    float c = 0.f, h = 0.f;
    int jg = 0, bg = 0;
    const float *xp0 = xg, *xp1 = xg, *xp2 = xg, *xp3 = xg;
    if (tid < 256) {
        jg = jb * 8 + cj;
        bg = bb * 32 + cb;
        c = c0[bg * HID + jg];
        __stcg(&g_hbufT[0][jg * BS + bg], h0[(size_t)bg * HID + jg]);
        xp0 = xg + (size_t)(0 * HID + jg) * MROWS + bg;
        xp1 = xg + (size_t)(1 * HID + jg) * MROWS + bg;
        xp2 = xg + (size_t)(2 * HID + jg) * MROWS + bg;
        xp3 = xg + (size_t)(3 * HID + jg) * MROWS + bg;
    }

    unsigned int* myflag = &g_flagsB[bb][jb];
    const unsigned int* grpflags = &g_flagsB[bb][0];

    // initial barrier: publish h0, raise own flag to 1, wait for all 64
    __syncthreads();
    if (tid == 0) st_release(myflag, 1u);
    if (warp == 0) {
        while (true) {
            unsigned v0 = ld_acquire(grpflags + lane);
            unsigned v1 = ld_acquire(grpflags + lane + 32);
            if (__all_sync(0xffffffffu, (v0 >= 1u) && (v1 >= 1u))) break;
        }
    }
    __syncthreads();

    float vx0 = 0.f, vx1 = 0.f, vx2 = 0.f, vx3 = 0.f;
    if (tid < 256) {
        vx0 = __ldg(xp0); vx1 = __ldg(xp1); vx2 = __ldg(xp2); vx3 = __ldg(xp3);
    }

    const int hcol = bb * 32 + bh * 16 + bq * 4;
    const float* wrow = &w_sm[jl * WJ_STRIDE + k0b];
    const int pst = bh * BH_F4 + jl * 5 + bq;

    for (int t = 0; t < TS; t++) {
        const float* hT = g_hbufT[t & 1] + (size_t)k0b * BS + hcol;

        unsigned long long acc[2][4];
#pragma unroll
        for (int bp = 0; bp < 2; bp++)
#pragma unroll
            for (int g = 0; g < 4; g++) acc[bp][g] = 0ull;

#pragma unroll 2
        for (int ck = 0; ck < 16; ck++) {
            int kb = ck * 4;
            float4 hv0 = __ldcg((const float4*)(hT + (kb + 0) * BS));
            float4 hv1 = __ldcg((const float4*)(hT + (kb + 1) * BS));
            float4 hv2 = __ldcg((const float4*)(hT + (kb + 2) * BS));
            float4 hv3 = __ldcg((const float4*)(hT + (kb + 3) * BS));
            float4 wv0 = *(const float4*)(wrow + 0 * WG_STRIDE + kb);
            float4 wv1 = *(const float4*)(wrow + 1 * WG_STRIDE + kb);
            float4 wv2 = *(const float4*)(wrow + 2 * WG_STRIDE + kb);
            float4 wv3 = *(const float4*)(wrow + 3 * WG_STRIDE + kb);
#pragma unroll
            for (int kk = 0; kk < 4; kk++) {
                float4 hv = (kk == 0) ? hv0 : (kk == 1) ? hv1 : (kk == 2) ? hv2 : hv3;
                unsigned long long hlo = pack2(hv.x, hv.y);
                unsigned long long hhi = pack2(hv.z, hv.w);
                float w0s = (kk == 0) ? wv0.x : (kk == 1) ? wv0.y : (kk == 2) ? wv0.z : wv0.w;
                float w1s = (kk == 0) ? wv1.x : (kk == 1) ? wv1.y : (kk == 2) ? wv1.z : wv1.w;
                float w2s = (kk == 0) ? wv2.x : (kk == 1) ? wv2.y : (kk == 2) ? wv2.z : wv2.w;
                float w3s = (kk == 0) ? wv3.x : (kk == 1) ? wv3.y : (kk == 2) ? wv3.z : wv3.w;
                unsigned long long w0d = pack2(w0s, w0s);
                unsigned long long w1d = pack2(w1s, w1s);
                unsigned long long w2d = pack2(w2s, w2s);
                unsigned long long w3d = pack2(w3s, w3s);
                acc[0][0] = fma2(hlo, w0d, acc[0][0]); acc[1][0] = fma2(hhi, w0d, acc[1][0]);
                acc[0][1] = fma2(hlo, w1d, acc[0][1]); acc[1][1] = fma2(hhi, w1d, acc[1][1]);
                acc[0][2] = fma2(hlo, w2d, acc[0][2]); acc[1][2] = fma2(hhi, w2d, acc[1][2]);
                acc[0][3] = fma2(hlo, w3d, acc[0][3]); acc[1][3] = fma2(hhi, w3d, acc[1][3]);
            }
        }

#pragma unroll
        for (int g = 0; g < 4; g++) {
            float2 lo = unpack2(acc[0][g]);
            float2 hi = unpack2(acc[1][g]);
            float4 v; v.x = lo.x; v.y = lo.y; v.z = hi.x; v.w = hi.y;
            ((float4*)p_sm)[(kq * 4 + g) * SEG_F4 + pst] = v;
        }
        __syncthreads();

        if (tid < 256) {
            int boff = (cb >> 4) * 176 + (cb & 15);
            float r0 = vx0, r1 = vx1, r2 = vx2, r3 = vx3;
#pragma unroll
            for (int q = 0; q < 8; q++) {
                int base = q * 4 * SEG_F4 * 4 + boff + cj * 20;
                r0 += p_sm[base + 0 * SEG_F4 * 4];
                r1 += p_sm[base + 1 * SEG_F4 * 4];
                r2 += p_sm[base + 2 * SEG_F4 * 4];
                r3 += p_sm[base + 3 * SEG_F4 * 4];
            }
            float ig = fsigmoid_(r0);
            float fg = fsigmoid_(r1);
            float gg = ftanh_(r2);
            float og = fsigmoid_(r3);
            c = fg * c + ig * gg;
            h = og * ftanh_(c);
            __stcg(&g_hbufT[(t + 1) & 1][jg * BS + bg], h);
        }
        __syncthreads();                     // all publishes done
        if (tid == 0) st_release(myflag, (unsigned)(t + 2));

        // overlap with barrier wait: out store + next-step xg prefetch
        if (tid < 256) {
            out[((size_t)t * BS + bg) * HID + jg] = h;
            if (t + 1 < TS) {
                int toff = (t + 1) * BS;
                vx0 = __ldg(xp0 + toff);
                vx1 = __ldg(xp1 + toff);
                vx2 = __ldg(xp2 + toff);
                vx3 = __ldg(xp3 + toff);
            }
        }
        // warp 0 polls all 64 flags lane-parallel (2 cache lines)
        if (warp == 0) {
            unsigned tgt = (unsigned)(t + 2);
            while (true) {
                unsigned v0 = ld_acquire(grpflags + lane);
                unsigned v1 = ld_acquire(grpflags + lane + 32);
                if (__all_sync(0xffffffffu, (v0 >= tgt) && (v1 >= tgt))) break;
            }
        }
        __syncthreads();
    }

    if (tid < 256) {
        hn[(size_t)bg * HID + jg] = h;
        cn[(size_t)bg * HID + jg] = c;
    }
}

// ---------------- launch ----------------------------------------------------
extern "C" void kernel_launch(void* const* d_in, const int* in_sizes, int n_in,
                              void* d_out, int out_size)
{
    const float* x    = (const float*)d_in[0];
    const float* h0   = (const float*)d_in[1];
    const float* c0   = (const float*)d_in[2];
    const float* W_ih = (const float*)d_in[3];
    const float* W_hh = (const float*)d_in[4];
    const float* b_ih = (const float*)d_in[5];
    const float* b_hh = (const float*)d_in[6];
    float* out = (float*)d_out;

    cudaFuncSetAttribute(lstm_kernel, cudaFuncAttributeMaxDynamicSharedMemorySize, LSTM_SMEM);
    cudaFuncSetAttribute(gemm_mma, cudaFuncAttributeMaxDynamicSharedMemorySize, GSMEM);

    void* pv;
    cudaGetSymbolAddress(&pv, g_out1);  float* p_out1 = (float*)pv;
    cudaGetSymbolAddress(&pv, g_xgates); const float* p_xg = (const float*)pv;
    cudaGetSymbolAddress(&pv, g_xhi);   __nv_bfloat16* p_xhi = (__nv_bfloat16*)pv;
    cudaGetSymbolAddress(&pv, g_xlo);   __nv_bfloat16* p_xlo = (__nv_bfloat16*)pv;
    cudaGetSymbolAddress(&pv, g_whi);   __nv_bfloat16* p_whi = (__nv_bfloat16*)pv;
    cudaGetSymbolAddress(&pv, g_wlo);   __nv_bfloat16* p_wlo = (__nv_bfloat16*)pv;

    dim3 ggrid(G4 / 128, MROWS / 128);   // (16, 512)

    // Layer 0
    convert_split<<<2048, 256>>>(x, p_xhi, p_xlo, (size_t)MROWS * HID, 1);
    convert_split<<<256, 256>>>(W_ih, p_whi, p_wlo, (size_t)G4 * HID, 0);
    gemm_mma<<<ggrid, 512, GSMEM>>>(p_xhi, p_xlo, p_whi, p_wlo, b_ih, b_hh);
    lstm_kernel<<<NCTA, LTHREADS, LSTM_SMEM>>>(
        W_hh, h0, c0, p_xg, p_out1,
        out + TBH, out + TBH + 2 * (size_t)BH);

    // Layer 1
    convert_split<<<2048, 256>>>(p_out1, p_xhi, p_xlo, (size_t)MROWS * HID, 1);
    convert_split<<<256, 256>>>(W_ih + (size_t)G4 * HID, p_whi, p_wlo, (size_t)G4 * HID, 0);
    gemm_mma<<<ggrid, 512, GSMEM>>>(p_xhi, p_xlo, p_whi, p_wlo, b_ih + G4, b_hh + G4);
    lstm_kernel<<<NCTA, LTHREADS, LSTM_SMEM>>>(
        W_hh + (size_t)G4 * HID, h0 + BH, c0 + BH, p_xg, out,
        out + TBH + (size_t)BH, out + TBH + 3 * (size_t)BH);

    (void)in_sizes; (void)n_in; (void)out_size;
}

// round 16
// speedup vs baseline: 1.7434x; 1.7434x over previous
#include <cuda_runtime.h>
#include <cuda_bf16.h>
#include <math.h>

#define TS   1024
#define BS   64
#define HID  512
#define G4   2048
#define NCTA 128
#define NGRP 64
#define LTHREADS 512
#define MROWS 65536
#define TBH  ((size_t)TS * BS * HID)
#define BH   (BS * HID)

// ---- lstm smem ----
#define WJ_STRIDE 2052
#define WG_STRIDE 512
#define P_OFF     (8 * WJ_STRIDE)
#define SEG_F4    88
#define BH_F4     44
#define P_FLOATS  (32 * SEG_F4 * 4)
#define O_OFF     (P_OFF + P_FLOATS)
#define LSTM_SMEM ((O_OFF + 288) * 4)

// ---- mma gemm smem (bf16 units / bytes) ----
#define AS_STRIDE 72
#define GS_AHI    0
#define GS_ALO    18432
#define GS_BHI    36864
#define GS_BLO    55296
#define GS_BIAS   73728
#define GSMEM     (73728 + 512)
#define DS_STRIDE 132

// Scratch (device globals)
__device__ float g_xgates[(size_t)G4 * MROWS];     // transposed [col][row]
__device__ float g_out1[(size_t)TS * BS * HID];
__device__ float g_hbufT[2][HID * BS];             // transposed h: [k][b]
__device__ unsigned int g_barG[2];
__device__ __nv_bfloat16 g_whi[(size_t)G4 * HID];
__device__ __nv_bfloat16 g_wlo[(size_t)G4 * HID];

// ---- packed f32x2 helpers ----
__device__ __forceinline__ unsigned long long fma2(unsigned long long a,
                                                   unsigned long long b,
                                                   unsigned long long c) {
    unsigned long long d;
    asm("fma.rn.f32x2 %0, %1, %2, %3;" : "=l"(d) : "l"(a), "l"(b), "l"(c));
    return d;
}
__device__ __forceinline__ unsigned long long pack2(float x, float y) {
    unsigned long long d;
    asm("mov.b64 %0, {%1, %2};" : "=l"(d) : "f"(x), "f"(y));
    return d;
}
__device__ __forceinline__ float2 unpack2(unsigned long long v) {
    float2 r;
    asm("mov.b64 {%0, %1}, %2;" : "=f"(r.x), "=f"(r.y) : "l"(v));
    return r;
}
__device__ __forceinline__ void red_release_add(unsigned int* p, unsigned int v) {
    asm volatile("red.release.gpu.global.add.u32 [%0], %1;" :: "l"(p), "r"(v) : "memory");
}
__device__ __forceinline__ unsigned int ld_acquire(const unsigned int* p) {
    unsigned int v;
    asm volatile("ld.acquire.gpu.global.u32 %0, [%1];" : "=r"(v) : "l"(p) : "memory");
    return v;
}
// fast activations (MUFU-based; error ~1e-6 vs 1e-3 budget, validated R14)
__device__ __forceinline__ float fsigmoid_(float x) {
    return __fdividef(1.f, 1.f + __expf(-x));
}
__device__ __forceinline__ float ftanh_(float x) {
    return 1.f - __fdividef(2.f, 1.f + __expf(2.f * x));
}

__device__ __forceinline__ void mma16816(float* d, const unsigned* a, const unsigned* b) {
    asm volatile(
        "mma.sync.aligned.m16n8k16.row.col.f32.bf16.bf16.f32 "
        "{%0,%1,%2,%3}, {%4,%5,%6,%7}, {%8,%9}, {%0,%1,%2,%3};"
        : "+f"(d[0]), "+f"(d[1]), "+f"(d[2]), "+f"(d[3])
        : "r"(a[0]), "r"(a[1]), "r"(a[2]), "r"(a[3]), "r"(b[0]), "r"(b[1]));
}

// split 8 fp32 -> bf16 hi/lo packed as uint4 each
__device__ __forceinline__ void split_f8(float4 p, float4 q, uint4& hi, uint4& lo) {
    float f[8] = {p.x, p.y, p.z, p.w, q.x, q.y, q.z, q.w};
    unsigned h[4], l[4];
#pragma unroll
    for (int i = 0; i < 4; i++) {
        __nv_bfloat16 h0 = __float2bfloat16(f[2 * i]);
        __nv_bfloat16 h1 = __float2bfloat16(f[2 * i + 1]);
        __nv_bfloat16 l0 = __float2bfloat16(f[2 * i] - __bfloat162float(h0));
        __nv_bfloat16 l1 = __float2bfloat16(f[2 * i + 1] - __bfloat162float(h1));
        __nv_bfloat162 hp, lp;
        hp.x = h0; hp.y = h1; lp.x = l0; lp.y = l1;
        h[i] = *(unsigned*)&hp; l[i] = *(unsigned*)&lp;
    }
    hi = make_uint4(h[0], h[1], h[2], h[3]);
    lo = make_uint4(l[0], l[1], l[2], l[3]);
}

// ---------------------------------------------------------------------------
// W split-convert fp32 -> bf16 hi/lo; also resets the recurrence barrier.
// ---------------------------------------------------------------------------
__global__ void convert_split(const float* __restrict__ src,
                              __nv_bfloat16* __restrict__ hi,
                              __nv_bfloat16* __restrict__ lo,
                              size_t n, int reset)
{
    if (reset && blockIdx.x == 0 && threadIdx.x == 0) {
        g_barG[0] = 0u; g_barG[1] = 0u;
    }
    size_t stride = (size_t)gridDim.x * blockDim.x;
    for (size_t i = (size_t)blockIdx.x * blockDim.x + threadIdx.x; i < n; i += stride) {
        float v = src[i];
        __nv_bfloat16 h = __float2bfloat16(v);
        hi[i] = h;
        lo[i] = __float2bfloat16(v - __bfloat162float(h));
    }
}

// ---------------------------------------------------------------------------
// bf16-split projection GEMM via mma.sync, k-block register-prefetch pipeline.
// A read as fp32 (x / out1) and split to bf16 hi/lo in-register at staging;
// B (weights) preconverted. Structure otherwise identical to R12 winner.
// ---------------------------------------------------------------------------
__global__ __launch_bounds__(512, 1) void gemm_mma(
    const float* __restrict__ A,
    const __nv_bfloat16* __restrict__ Bhi, const __nv_bfloat16* __restrict__ Blo,
    const float* __restrict__ b1, const float* __restrict__ b2)
{
    extern __shared__ char smem[];
    __nv_bfloat16* As_hi = (__nv_bfloat16*)(smem + GS_AHI);
    __nv_bfloat16* As_lo = (__nv_bfloat16*)(smem + GS_ALO);
    __nv_bfloat16* Bs_hi = (__nv_bfloat16*)(smem + GS_BHI);
    __nv_bfloat16* Bs_lo = (__nv_bfloat16*)(smem + GS_BLO);
    float* bias_sm = (float*)(smem + GS_BIAS);
    float* Ds = (float*)smem;

    const int tid  = threadIdx.x;
    const int warp = tid >> 5;
    const int lane = tid & 31;
    const int wm = (warp & 3) * 32;
    const int wn = (warp >> 2) * 32;
    const int g0 = blockIdx.x * 128;
    const int m0 = blockIdx.y * 128;

    for (int i = tid; i < 128; i += 512)
        bias_sm[i] = b1[g0 + i] + b2[g0 + i];

    float d[2][4][4];
#pragma unroll
    for (int fi = 0; fi < 2; fi++)
#pragma unroll
        for (int fj = 0; fj < 4; fj++)
#pragma unroll
            for (int r = 0; r < 4; r++) d[fi][fj][r] = 0.f;

    const int lr = lane >> 2;
    const int lc = lane & 3;

    const int row0 = tid >> 3,         c0 = tid & 7;
    const int row1 = (tid + 512) >> 3, c1 = (tid + 512) & 7;
    const size_t a0base = (size_t)(m0 + row0) * HID + c0 * 8;
    const size_t a1base = (size_t)(m0 + row1) * HID + c1 * 8;
    const size_t b0base = (size_t)(g0 + row0) * HID + c0 * 8;
    const size_t b1base = (size_t)(g0 + row1) * HID + c1 * 8;
    const int d0 = row0 * AS_STRIDE + c0 * 8;
    const int d1 = row1 * AS_STRIDE + c1 * 8;

    float4 fa00, fa01, fa10, fa11;     // fp32 A prefetch (2 chunks x 8 floats)
    float4 rbh0, rbh1, rbl0, rbl1;     // bf16 B prefetch
    {
        fa00 = *(const float4*)(A + a0base); fa01 = *(const float4*)(A + a0base + 4);
        fa10 = *(const float4*)(A + a1base); fa11 = *(const float4*)(A + a1base + 4);
        rbh0 = *(const float4*)(Bhi + b0base); rbh1 = *(const float4*)(Bhi + b1base);
        rbl0 = *(const float4*)(Blo + b0base); rbl1 = *(const float4*)(Blo + b1base);
    }

    for (int kb = 0; kb < 8; kb++) {
        __syncthreads();
        {
            uint4 hi0, lo0, hi1, lo1;
            split_f8(fa00, fa01, hi0, lo0);
            split_f8(fa10, fa11, hi1, lo1);
            *(uint4*)(As_hi + d0) = hi0; *(uint4*)(As_lo + d0) = lo0;
            *(uint4*)(As_hi + d1) = hi1; *(uint4*)(As_lo + d1) = lo1;
        }
        *(float4*)(Bs_hi + d0) = rbh0; *(float4*)(Bs_hi + d1) = rbh1;
        *(float4*)(Bs_lo + d0) = rbl0; *(float4*)(Bs_lo + d1) = rbl1;
        __syncthreads();

        if (kb < 7) {
            const int k0 = (kb + 1) * 64;
            fa00 = *(const float4*)(A + a0base + k0); fa01 = *(const float4*)(A + a0base + k0 + 4);
            fa10 = *(const float4*)(A + a1base + k0); fa11 = *(const float4*)(A + a1base + k0 + 4);
            rbh0 = *(const float4*)(Bhi + b0base + k0); rbh1 = *(const float4*)(Bhi + b1base + k0);
            rbl0 = *(const float4*)(Blo + b0base + k0); rbl1 = *(const float4*)(Blo + b1base + k0);
        }

#pragma unroll
        for (int ks = 0; ks < 4; ks++) {
            const int kc = ks * 16 + lc * 2;
            unsigned ah[2][4], al[2][4];
#pragma unroll
            for (int fi = 0; fi < 2; fi++) {
                int base = (wm + fi * 16 + lr) * AS_STRIDE;
                ah[fi][0] = *(const unsigned*)(As_hi + base + kc);
                ah[fi][1] = *(const unsigned*)(As_hi + base + 8 * AS_STRIDE + kc);
                ah[fi][2] = *(const unsigned*)(As_hi + base + kc + 8);
                ah[fi][3] = *(const unsigned*)(As_hi + base + 8 * AS_STRIDE + kc + 8);
                al[fi][0] = *(const unsigned*)(As_lo + base + kc);
                al[fi][1] = *(const unsigned*)(As_lo + base + 8 * AS_STRIDE + kc);
                al[fi][2] = *(const unsigned*)(As_lo + base + kc + 8);
                al[fi][3] = *(const unsigned*)(As_lo + base + 8 * AS_STRIDE + kc + 8);
            }
            unsigned bh[4][2], bl[4][2];
#pragma unroll
            for (int fj = 0; fj < 4; fj++) {
                int base = (wn + fj * 8 + lr) * AS_STRIDE;
                bh[fj][0] = *(const unsigned*)(Bs_hi + base + kc);
                bh[fj][1] = *(const unsigned*)(Bs_hi + base + kc + 8);
                bl[fj][0] = *(const unsigned*)(Bs_lo + base + kc);
                bl[fj][1] = *(const unsigned*)(Bs_lo + base + kc + 8);
            }
#pragma unroll
            for (int fi = 0; fi < 2; fi++)
#pragma unroll
                for (int fj = 0; fj < 4; fj++) {
                    mma16816(d[fi][fj], ah[fi], bh[fj]);
                    mma16816(d[fi][fj], ah[fi], bl[fj]);
                    mma16816(d[fi][fj], al[fi], bh[fj]);
                }
        }
    }

    __syncthreads();
#pragma unroll
    for (int fi = 0; fi < 2; fi++)
#pragma unroll
        for (int fj = 0; fj < 4; fj++) {
            int r = wm + fi * 16 + lr;
            int c = wn + fj * 8 + lc * 2;
            Ds[(c + 0) * DS_STRIDE + r]     = d[fi][fj][0];
            Ds[(c + 1) * DS_STRIDE + r]     = d[fi][fj][1];
            Ds[(c + 0) * DS_STRIDE + r + 8] = d[fi][fj][2];
            Ds[(c + 1) * DS_STRIDE + r + 8] = d[fi][fj][3];
        }
    __syncthreads();
#pragma unroll
    for (int idx = tid; idx < 128 * 32; idx += 512) {
        int col = idx >> 5, ch = idx & 31;
        float4 v = *(const float4*)(Ds + col * DS_STRIDE + ch * 4);
        float b = bias_sm[col];
        v.x += b; v.y += b; v.z += b; v.w += b;
        *(float4*)(g_xgates + (size_t)(g0 + col) * MROWS + m0 + ch * 4) = v;
    }
}

// ---------------------------------------------------------------------------
// Persistent recurrence — R14 winner (frozen barrier), plus coalesced out[]
// stores via a padded smem transpose tile (full-sector 32B warp writes).
// ---------------------------------------------------------------------------
__global__ __launch_bounds__(LTHREADS, 1) void lstm_kernel(
    const float* __restrict__ Whh, const float* __restrict__ h0,
    const float* __restrict__ c0, const float* __restrict__ xg,
    float* __restrict__ out, float* __restrict__ hn, float* __restrict__ cn)
{
    extern __shared__ float sm[];
    float* w_sm = sm;
    float* p_sm = sm + P_OFF;
    float* o_sm = sm + O_OFF;          // [32 b][stride 9] h staging

    const int tid  = threadIdx.x;
    const int cta  = blockIdx.x;
    const int jb   = cta & 63;
    const int bb   = cta >> 6;
    const int warp = tid >> 5;
    const int lane = tid & 31;
    const int bh = warp & 1;
    const int kq = warp >> 1;
    const int bq = lane & 3;
    const int jl = lane >> 2;
    const int k0b = kq * 64;
    const int cj = warp;
    const int cb = lane;

    unsigned int* bar = &g_barG[bb];

    {
        const float4* Wsrc = (const float4*)Whh;
#pragma unroll
        for (int idx = tid; idx < 4096; idx += LTHREADS) {
            int wj = idx >> 9, g = (idx >> 7) & 3, k4 = idx & 127;
            *(float4*)&w_sm[wj * WJ_STRIDE + g * WG_STRIDE + k4 * 4] =
                Wsrc[(((size_t)(g * HID + jb * 8 + wj)) * HID >> 2) + k4];
        }
    }

    float c = 0.f, h = 0.f;
    int jg = 0, bg = 0;
    const float *xp0 = xg, *xp1 = xg, *xp2 = xg, *xp3 = xg;
    if (tid < 256) {
        jg = jb * 8 + cj;
        bg = bb * 32 + cb;
        c = c0[bg * HID + jg];
        __stcg(&g_hbufT[0][jg * BS + bg], h0[(size_t)bg * HID + jg]);
        xp0 = xg + (size_t)(0 * HID + jg) * MROWS + bg;
        xp1 = xg + (size_t)(1 * HID + jg) * MROWS + bg;
        xp2 = xg + (size_t)(2 * HID + jg) * MROWS + bg;
        xp3 = xg + (size_t)(3 * HID + jg) * MROWS + bg;
    }

    unsigned expect = 0;
    __syncthreads();
    if (tid == 0) {
        red_release_add(bar, 1u);
        expect += NGRP;
        while (ld_acquire(bar) < expect) { }
    }
    __syncthreads();

    float vx0 = 0.f, vx1 = 0.f, vx2 = 0.f, vx3 = 0.f;
    if (tid < 256) {
        vx0 = __ldg(xp0); vx1 = __ldg(xp1); vx2 = __ldg(xp2); vx3 = __ldg(xp3);
    }

    const int hcol = bb * 32 + bh * 16 + bq * 4;
    const float* wrow = &w_sm[jl * WJ_STRIDE + k0b];
    const int pst = bh * BH_F4 + jl * 5 + bq;
    const int orow = tid >> 3, ocol = tid & 7;   // out-store remap (tid<256)

    for (int t = 0; t < TS; t++) {
        const float* hT = g_hbufT[t & 1] + (size_t)k0b * BS + hcol;

        unsigned long long acc[2][4];
#pragma unroll
        for (int bp = 0; bp < 2; bp++)
#pragma unroll
            for (int g = 0; g < 4; g++) acc[bp][g] = 0ull;

#pragma unroll 2
        for (int ck = 0; ck < 16; ck++) {
            int kb = ck * 4;
            float4 hv0 = __ldcg((const float4*)(hT + (kb + 0) * BS));
            float4 hv1 = __ldcg((const float4*)(hT + (kb + 1) * BS));
            float4 hv2 = __ldcg((const float4*)(hT + (kb + 2) * BS));
            float4 hv3 = __ldcg((const float4*)(hT + (kb + 3) * BS));
            float4 wv0 = *(const float4*)(wrow + 0 * WG_STRIDE + kb);
            float4 wv1 = *(const float4*)(wrow + 1 * WG_STRIDE + kb);
            float4 wv2 = *(const float4*)(wrow + 2 * WG_STRIDE + kb);
            float4 wv3 = *(const float4*)(wrow + 3 * WG_STRIDE + kb);
#pragma unroll
            for (int kk = 0; kk < 4; kk++) {
                float4 hv = (kk == 0) ? hv0 : (kk == 1) ? hv1 : (kk == 2) ? hv2 : hv3;
                unsigned long long hlo = pack2(hv.x, hv.y);
                unsigned long long hhi = pack2(hv.z, hv.w);
                float w0s = (kk == 0) ? wv0.x : (kk == 1) ? wv0.y : (kk == 2) ? wv0.z : wv0.w;
                float w1s = (kk == 0) ? wv1.x : (kk == 1) ? wv1.y : (kk == 2) ? wv1.z : wv1.w;
                float w2s = (kk == 0) ? wv2.x : (kk == 1) ? wv2.y : (kk == 2) ? wv2.z : wv2.w;
                float w3s = (kk == 0) ? wv3.x : (kk == 1) ? wv3.y : (kk == 2) ? wv3.z : wv3.w;
                unsigned long long w0d = pack2(w0s, w0s);
                unsigned long long w1d = pack2(w1s, w1s);
                unsigned long long w2d = pack2(w2s, w2s);
                unsigned long long w3d = pack2(w3s, w3s);
                acc[0][0] = fma2(hlo, w0d, acc[0][0]); acc[1][0] = fma2(hhi, w0d, acc[1][0]);
                acc[0][1] = fma2(hlo, w1d, acc[0][1]); acc[1][1] = fma2(hhi, w1d, acc[1][1]);
                acc[0][2] = fma2(hlo, w2d, acc[0][2]); acc[1][2] = fma2(hhi, w2d, acc[1][2]);
                acc[0][3] = fma2(hlo, w3d, acc[0][3]); acc[1][3] = fma2(hhi, w3d, acc[1][3]);
            }
        }

#pragma unroll
        for (int g = 0; g < 4; g++) {
            float2 lo = unpack2(acc[0][g]);
            float2 hi = unpack2(acc[1][g]);
            float4 v; v.x = lo.x; v.y = lo.y; v.z = hi.x; v.w = hi.y;
            ((float4*)p_sm)[(kq * 4 + g) * SEG_F4 + pst] = v;
        }
        __syncthreads();

        if (tid < 256) {
            int boff = (cb >> 4) * 176 + (cb & 15);
            float r0 = vx0, r1 = vx1, r2 = vx2, r3 = vx3;
#pragma unroll
            for (int q = 0; q < 8; q++) {
                int base = q * 4 * SEG_F4 * 4 + boff + cj * 20;
                r0 += p_sm[base + 0 * SEG_F4 * 4];
                r1 += p_sm[base + 1 * SEG_F4 * 4];
                r2 += p_sm[base + 2 * SEG_F4 * 4];
                r3 += p_sm[base + 3 * SEG_F4 * 4];
            }
            float ig = fsigmoid_(r0);
            float fg = fsigmoid_(r1);
            float gg = ftanh_(r2);
            float og = fsigmoid_(r3);
            c = fg * c + ig * gg;
            h = og * ftanh_(c);
            __stcg(&g_hbufT[(t + 1) & 1][jg * BS + bg], h);
            o_sm[cb * 9 + cj] = h;          // stage for coalesced out store
        }
        __syncthreads();
        if (tid == 0) {
            red_release_add(bar, 1u);
            expect += NGRP;
        }
        if (tid < 256) {
            // coalesced: warp writes 4 full 32B sectors
            out[((size_t)t * BS + bb * 32 + orow) * HID + jb * 8 + ocol] =
                o_sm[orow * 9 + ocol];
            if (t + 1 < TS) {
                int toff = (t + 1) * BS;
                vx0 = __ldg(xp0 + toff);
                vx1 = __ldg(xp1 + toff);
                vx2 = __ldg(xp2 + toff);
                vx3 = __ldg(xp3 + toff);
            }
        }
        if (tid == 0) {
            while (ld_acquire(bar) < expect) { }
        }
        __syncthreads();
    }

    if (tid < 256) {
        hn[(size_t)bg * HID + jg] = h;
        cn[(size_t)bg * HID + jg] = c;
    }
}

// ---------------- launch ----------------------------------------------------
extern "C" void kernel_launch(void* const* d_in, const int* in_sizes, int n_in,
                              void* d_out, int out_size)
{
    const float* x    = (const float*)d_in[0];
    const float* h0   = (const float*)d_in[1];
    const float* c0   = (const float*)d_in[2];
    const float* W_ih = (const float*)d_in[3];
    const float* W_hh = (const float*)d_in[4];
    const float* b_ih = (const float*)d_in[5];
    const float* b_hh = (const float*)d_in[6];
    float* out = (float*)d_out;

    cudaFuncSetAttribute(lstm_kernel, cudaFuncAttributeMaxDynamicSharedMemorySize, LSTM_SMEM);
    cudaFuncSetAttribute(gemm_mma, cudaFuncAttributeMaxDynamicSharedMemorySize, GSMEM);

    void* pv;
    cudaGetSymbolAddress(&pv, g_out1);  float* p_out1 = (float*)pv;
    cudaGetSymbolAddress(&pv, g_xgates); const float* p_xg = (const float*)pv;
    cudaGetSymbolAddress(&pv, g_whi);   __nv_bfloat16* p_whi = (__nv_bfloat16*)pv;
    cudaGetSymbolAddress(&pv, g_wlo);   __nv_bfloat16* p_wlo = (__nv_bfloat16*)pv;

    dim3 ggrid(G4 / 128, MROWS / 128);   // (16, 512)

    // Layer 0
    convert_split<<<256, 256>>>(W_ih, p_whi, p_wlo, (size_t)G4 * HID, 1);
    gemm_mma<<<ggrid, 512, GSMEM>>>(x, p_whi, p_wlo, b_ih, b_hh);
    lstm_kernel<<<NCTA, LTHREADS, LSTM_SMEM>>>(
        W_hh, h0, c0, p_xg, p_out1,
        out + TBH, out + TBH + 2 * (size_t)BH);

    // Layer 1
    convert_split<<<256, 256>>>(W_ih + (size_t)G4 * HID, p_whi, p_wlo, (size_t)G4 * HID, 1);
    gemm_mma<<<ggrid, 512, GSMEM>>>(p_out1, p_whi, p_wlo, b_ih + G4, b_hh + G4);
    lstm_kernel<<<NCTA, LTHREADS, LSTM_SMEM>>>(
        W_hh + (size_t)G4 * HID, h0 + BH, c0 + BH, p_xg, out,
        out + TBH + (size_t)BH, out + TBH + 3 * (size_t)BH);

    (void)in_sizes; (void)n_in; (void)out_size;
}

// round 17
// speedup vs baseline: 1.7829x; 1.0227x over previous
#include <cuda_runtime.h>
#include <cuda_bf16.h>
#include <math.h>

#define TS   1024
#define BS   64
#define HID  512
#define G4   2048
#define NCTA 128
#define NGRP 64
#define LTHREADS 512
#define MROWS 65536
#define TBH  ((size_t)TS * BS * HID)
#define BH   (BS * HID)

// ---- lstm smem (bytes) ----
#define SW     520                      // W smem row stride in bf16 (512+8)
#define W_BF   (32 * SW)                // 16640 bf16 per array
#define PS     36                       // partial row stride (floats)
#define P_F    (4 * 32 * PS)            // 4608 floats
#define LS_P_OFF   (2 * W_BF * 2)       // 66560 bytes
#define LS_OF_OFF  (LS_P_OFF + P_F * 4) // o_f32: 288 floats
#define LS_OH_OFF  (LS_OF_OFF + 288 * 4)
#define LS_OL_OFF  (LS_OH_OFF + 128 * 4)
#define LSTM_SMEM  (LS_OL_OFF + 128 * 4)   // ~87.7KB

// ---- mma gemm smem (unchanged R16) ----
#define AS_STRIDE 72
#define GS_AHI    0
#define GS_ALO    18432
#define GS_BHI    36864
#define GS_BLO    55296
#define GS_BIAS   73728
#define GSMEM     (73728 + 512)
#define DS_STRIDE 132

// Scratch (device globals)
__device__ float g_xgates[(size_t)G4 * MROWS];     // transposed [col][row]
__device__ float g_out1[(size_t)TS * BS * HID];
__device__ __nv_bfloat16 g_hbHi[2][BS * HID];      // h hi: [buf][b][k]
__device__ __nv_bfloat16 g_hbLo[2][BS * HID];      // h lo
__device__ unsigned int g_barG[2];
__device__ __nv_bfloat16 g_whi[(size_t)G4 * HID];  // W_ih split (per layer)
__device__ __nv_bfloat16 g_wlo[(size_t)G4 * HID];
__device__ __nv_bfloat16 g_rwhi[(size_t)G4 * HID]; // W_hh split (per layer)
__device__ __nv_bfloat16 g_rwlo[(size_t)G4 * HID];

// ---- helpers ----
__device__ __forceinline__ void red_release_add(unsigned int* p, unsigned int v) {
    asm volatile("red.release.gpu.global.add.u32 [%0], %1;" :: "l"(p), "r"(v) : "memory");
}
__device__ __forceinline__ unsigned int ld_acquire(const unsigned int* p) {
    unsigned int v;
    asm volatile("ld.acquire.gpu.global.u32 %0, [%1];" : "=r"(v) : "l"(p) : "memory");
    return v;
}
__device__ __forceinline__ unsigned ldcg_u32(const void* p) {
    unsigned v;
    asm volatile("ld.global.cg.b32 %0, [%1];" : "=r"(v) : "l"(p));
    return v;
}
__device__ __forceinline__ unsigned smem_u32(const void* p) {
    unsigned a;
    asm("{ .reg .u64 t; cvta.to.shared.u64 t, %1; cvt.u32.u64 %0, t; }" : "=r"(a) : "l"(p));
    return a;
}
__device__ __forceinline__ void ldmat4(unsigned* r, unsigned saddr) {
    asm volatile("ldmatrix.sync.aligned.m8n8.x4.shared.b16 {%0,%1,%2,%3}, [%4];"
                 : "=r"(r[0]), "=r"(r[1]), "=r"(r[2]), "=r"(r[3]) : "r"(saddr));
}
__device__ __forceinline__ float fsigmoid_(float x) {
    return __fdividef(1.f, 1.f + __expf(-x));
}
__device__ __forceinline__ float ftanh_(float x) {
    return 1.f - __fdividef(2.f, 1.f + __expf(2.f * x));
}
__device__ __forceinline__ void mma16816(float* d, const unsigned* a, const unsigned* b) {
    asm volatile(
        "mma.sync.aligned.m16n8k16.row.col.f32.bf16.bf16.f32 "
        "{%0,%1,%2,%3}, {%4,%5,%6,%7}, {%8,%9}, {%0,%1,%2,%3};"
        : "+f"(d[0]), "+f"(d[1]), "+f"(d[2]), "+f"(d[3])
        : "r"(a[0]), "r"(a[1]), "r"(a[2]), "r"(a[3]), "r"(b[0]), "r"(b[1]));
}
// split 8 fp32 -> bf16 hi/lo packed as uint4 each
__device__ __forceinline__ void split_f8(float4 p, float4 q, uint4& hi, uint4& lo) {
    float f[8] = {p.x, p.y, p.z, p.w, q.x, q.y, q.z, q.w};
    unsigned h[4], l[4];
#pragma unroll
    for (int i = 0; i < 4; i++) {
        __nv_bfloat16 h0 = __float2bfloat16(f[2 * i]);
        __nv_bfloat16 h1 = __float2bfloat16(f[2 * i + 1]);
        __nv_bfloat16 l0 = __float2bfloat16(f[2 * i] - __bfloat162float(h0));
        __nv_bfloat16 l1 = __float2bfloat16(f[2 * i + 1] - __bfloat162float(h1));
        __nv_bfloat162 hp, lp;
        hp.x = h0; hp.y = h1; lp.x = l0; lp.y = l1;
        h[i] = *(unsigned*)&hp; l[i] = *(unsigned*)&lp;
    }
    hi = make_uint4(h[0], h[1], h[2], h[3]);
    lo = make_uint4(l[0], l[1], l[2], l[3]);
}

// ---------------------------------------------------------------------------
// Split-convert fp32 -> bf16 hi/lo. Optionally resets barrier counters.
// ---------------------------------------------------------------------------
__global__ void convert_split(const float* __restrict__ src,
                              __nv_bfloat16* __restrict__ hi,
                              __nv_bfloat16* __restrict__ lo,
                              size_t n, int reset)
{
    if (reset && blockIdx.x == 0 && threadIdx.x == 0) {
        g_barG[0] = 0u; g_barG[1] = 0u;
    }
    size_t stride = (size_t)gridDim.x * blockDim.x;
    for (size_t i = (size_t)blockIdx.x * blockDim.x + threadIdx.x; i < n; i += stride) {
        float v = src[i];
        __nv_bfloat16 h = __float2bfloat16(v);
        hi[i] = h;
        lo[i] = __float2bfloat16(v - __bfloat162float(h));
    }
}

// ---------------------------------------------------------------------------
// bf16-split projection GEMM (verified R16 version, unchanged).
// ---------------------------------------------------------------------------
__global__ __launch_bounds__(512, 1) void gemm_mma(
    const float* __restrict__ A,
    const __nv_bfloat16* __restrict__ Bhi, const __nv_bfloat16* __restrict__ Blo,
    const float* __restrict__ b1, const float* __restrict__ b2)
{
    extern __shared__ char smem[];
    __nv_bfloat16* As_hi = (__nv_bfloat16*)(smem + GS_AHI);
    __nv_bfloat16* As_lo = (__nv_bfloat16*)(smem + GS_ALO);
    __nv_bfloat16* Bs_hi = (__nv_bfloat16*)(smem + GS_BHI);
    __nv_bfloat16* Bs_lo = (__nv_bfloat16*)(smem + GS_BLO);
    float* bias_sm = (float*)(smem + GS_BIAS);
    float* Ds = (float*)smem;

    const int tid  = threadIdx.x;
    const int warp = tid >> 5;
    const int lane = tid & 31;
    const int wm = (warp & 3) * 32;
    const int wn = (warp >> 2) * 32;
    const int g0 = blockIdx.x * 128;
    const int m0 = blockIdx.y * 128;

    for (int i = tid; i < 128; i += 512)
        bias_sm[i] = b1[g0 + i] + b2[g0 + i];

    float d[2][4][4];
#pragma unroll
    for (int fi = 0; fi < 2; fi++)
#pragma unroll
        for (int fj = 0; fj < 4; fj++)
#pragma unroll
            for (int r = 0; r < 4; r++) d[fi][fj][r] = 0.f;

    const int lr = lane >> 2;
    const int lc = lane & 3;

    const int row0 = tid >> 3,         c0 = tid & 7;
    const int row1 = (tid + 512) >> 3, c1 = (tid + 512) & 7;
    const size_t a0base = (size_t)(m0 + row0) * HID + c0 * 8;
    const size_t a1base = (size_t)(m0 + row1) * HID + c1 * 8;
    const size_t b0base = (size_t)(g0 + row0) * HID + c0 * 8;
    const size_t b1base = (size_t)(g0 + row1) * HID + c1 * 8;
    const int d0 = row0 * AS_STRIDE + c0 * 8;
    const int d1 = row1 * AS_STRIDE + c1 * 8;

    float4 fa00, fa01, fa10, fa11;
    float4 rbh0, rbh1, rbl0, rbl1;
    {
        fa00 = *(const float4*)(A + a0base); fa01 = *(const float4*)(A + a0base + 4);
        fa10 = *(const float4*)(A + a1base); fa11 = *(const float4*)(A + a1base + 4);
        rbh0 = *(const float4*)(Bhi + b0base); rbh1 = *(const float4*)(Bhi + b1base);
        rbl0 = *(const float4*)(Blo + b0base); rbl1 = *(const float4*)(Blo + b1base);
    }

    for (int kb = 0; kb < 8; kb++) {
        __syncthreads();
        {
            uint4 hi0, lo0, hi1, lo1;
            split_f8(fa00, fa01, hi0, lo0);
            split_f8(fa10, fa11, hi1, lo1);
            *(uint4*)(As_hi + d0) = hi0; *(uint4*)(As_lo + d0) = lo0;
            *(uint4*)(As_hi + d1) = hi1; *(uint4*)(As_lo + d1) = lo1;
        }
        *(float4*)(Bs_hi + d0) = rbh0; *(float4*)(Bs_hi + d1) = rbh1;
        *(float4*)(Bs_lo + d0) = rbl0; *(float4*)(Bs_lo + d1) = rbl1;
        __syncthreads();

        if (kb < 7) {
            const int k0 = (kb + 1) * 64;
            fa00 = *(const float4*)(A + a0base + k0); fa01 = *(const float4*)(A + a0base + k0 + 4);
            fa10 = *(const float4*)(A + a1base + k0); fa11 = *(const float4*)(A + a1base + k0 + 4);
            rbh0 = *(const float4*)(Bhi + b0base + k0); rbh1 = *(const float4*)(Bhi + b1base + k0);
            rbl0 = *(const float4*)(Blo + b0base + k0); rbl1 = *(const float4*)(Blo + b1base + k0);
        }

#pragma unroll
        for (int ks = 0; ks < 4; ks++) {
            const int kc = ks * 16 + lc * 2;
            unsigned ah[2][4], al[2][4];
#pragma unroll
            for (int fi = 0; fi < 2; fi++) {
                int base = (wm + fi * 16 + lr) * AS_STRIDE;
                ah[fi][0] = *(const unsigned*)(As_hi + base + kc);
                ah[fi][1] = *(const unsigned*)(As_hi + base + 8 * AS_STRIDE + kc);
                ah[fi][2] = *(const unsigned*)(As_hi + base + kc + 8);
                ah[fi][3] = *(const unsigned*)(As_hi + base + 8 * AS_STRIDE + kc + 8);
                al[fi][0] = *(const unsigned*)(As_lo + base + kc);
                al[fi][1] = *(const unsigned*)(As_lo + base + 8 * AS_STRIDE + kc);
                al[fi][2] = *(const unsigned*)(As_lo + base + kc + 8);
                al[fi][3] = *(const unsigned*)(As_lo + base + 8 * AS_STRIDE + kc + 8);
            }
            unsigned bh[4][2], bl[4][2];
#pragma unroll
            for (int fj = 0; fj < 4; fj++) {
                int base = (wn + fj * 8 + lr) * AS_STRIDE;
                bh[fj][0] = *(const unsigned*)(Bs_hi + base + kc);
                bh[fj][1] = *(const unsigned*)(Bs_hi + base + kc + 8);
                bl[fj][0] = *(const unsigned*)(Bs_lo + base + kc);
                bl[fj][1] = *(const unsigned*)(Bs_lo + base + kc + 8);
            }
#pragma unroll
            for (int fi = 0; fi < 2; fi++)
#pragma unroll
                for (int fj = 0; fj < 4; fj++) {
                    mma16816(d[fi][fj], ah[fi], bh[fj]);
                    mma16816(d[fi][fj], ah[fi], bl[fj]);
                    mma16816(d[fi][fj], al[fi], bh[fj]);
                }
        }
    }

    __syncthreads();
#pragma unroll
    for (int fi = 0; fi < 2; fi++)
#pragma unroll
        for (int fj = 0; fj < 4; fj++) {
            int r = wm + fi * 16 + lr;
            int c = wn + fj * 8 + lc * 2;
            Ds[(c + 0) * DS_STRIDE + r]     = d[fi][fj][0];
            Ds[(c + 1) * DS_STRIDE + r]     = d[fi][fj][1];
            Ds[(c + 0) * DS_STRIDE + r + 8] = d[fi][fj][2];
            Ds[(c + 1) * DS_STRIDE + r + 8] = d[fi][fj][3];
        }
    __syncthreads();
#pragma unroll
    for (int idx = tid; idx < 128 * 32; idx += 512) {
        int col = idx >> 5, ch = idx & 31;
        float4 v = *(const float4*)(Ds + col * DS_STRIDE + ch * 4);
        float b = bias_sm[col];
        v.x += b; v.y += b; v.z += b; v.w += b;
        *(float4*)(g_xgates + (size_t)(g0 + col) * MROWS + m0 + ch * 4) = v;
    }
}

// ---------------------------------------------------------------------------
// Persistent recurrence with TENSOR-CORE dot (bf16-split, 3 products).
// Per CTA/step: D[32 m=(gate*8+j)][32 n=b] = W[32][512] x h[512][32].
// 16 warps = 4 ni x 4 kq; warp: 2 m-tiles x n8 x 8 ksteps x 3 mma.
// A (W) via ldmatrix from smem; B (h bf16 hi/lo, [b][k]) via ld.global.cg.
// Barrier = frozen R14 central 2-counter.
// ---------------------------------------------------------------------------
__global__ __launch_bounds__(LTHREADS, 1) void lstm_kernel(
    const __nv_bfloat16* __restrict__ rwhi, const __nv_bfloat16* __restrict__ rwlo,
    const float* __restrict__ h0, const float* __restrict__ c0,
    const float* __restrict__ xg,
    float* __restrict__ out, float* __restrict__ hn, float* __restrict__ cn)
{
    extern __shared__ char smc[];
    __nv_bfloat16* whi_sm = (__nv_bfloat16*)smc;
    __nv_bfloat16* wlo_sm = whi_sm + W_BF;
    float* p_sm  = (float*)(smc + LS_P_OFF);
    float* o_f32 = (float*)(smc + LS_OF_OFF);
    unsigned* o_hi = (unsigned*)(smc + LS_OH_OFF);
    unsigned* o_lo = (unsigned*)(smc + LS_OL_OFF);

    const int tid  = threadIdx.x;
    const int cta  = blockIdx.x;
    const int jb   = cta & 63;
    const int bb   = cta >> 6;
    const int warp = tid >> 5;
    const int lane = tid & 31;
    const int ni = warp & 3;         // n-slice (8 b)
    const int kq = warp >> 2;        // k-quarter (128 k)
    const int cj = warp;             // cell role (warps 0-7): j
    const int cb = lane;             // cell role: b

    unsigned int* bar = &g_barG[bb];

    // load W slice (32 rows: m = g*8+jl -> global row g*512 + jb*8 + jl)
    for (int idx = tid; idx < 2048; idx += LTHREADS) {
        int m = idx >> 6, kc = idx & 63;
        size_t src = ((size_t)((m >> 3) * 512 + jb * 8 + (m & 7))) * HID + kc * 8;
        *(uint4*)(whi_sm + m * SW + kc * 8) = *(const uint4*)(rwhi + src);
        *(uint4*)(wlo_sm + m * SW + kc * 8) = *(const uint4*)(rwlo + src);
    }

    float c = 0.f, h = 0.f;
    int jg = 0, bg = 0;
    const float *xp0 = xg, *xp1 = xg, *xp2 = xg, *xp3 = xg;
    if (tid < 256) {
        jg = jb * 8 + cj;
        bg = bb * 32 + cb;
        c = c0[bg * HID + jg];
        float h0v = h0[(size_t)bg * HID + jg];
        __nv_bfloat16 hh = __float2bfloat16(h0v);
        __nv_bfloat16 hl = __float2bfloat16(h0v - __bfloat162float(hh));
        g_hbHi[0][bg * HID + jg] = hh;
        g_hbLo[0][bg * HID + jg] = hl;
        xp0 = xg + (size_t)(0 * HID + jg) * MROWS + bg;
        xp1 = xg + (size_t)(1 * HID + jg) * MROWS + bg;
        xp2 = xg + (size_t)(2 * HID + jg) * MROWS + bg;
        xp3 = xg + (size_t)(3 * HID + jg) * MROWS + bg;
    }

    unsigned expect = 0;
    __syncthreads();
    if (tid == 0) {
        red_release_add(bar, 1u);
        expect += NGRP;
        while (ld_acquire(bar) < expect) { }
    }
    __syncthreads();

    float vx0 = 0.f, vx1 = 0.f, vx2 = 0.f, vx3 = 0.f;
    if (tid < 256) {
        vx0 = __ldg(xp0); vx1 = __ldg(xp1); vx2 = __ldg(xp2); vx3 = __ldg(xp3);
    }

    // ldmatrix lane bases (bytes, shared space)
    const unsigned whiB = smem_u32(whi_sm);
    const unsigned wloB = smem_u32(wlo_sm);
    const int lrow = lane & 15;
    const int lk8  = (lane >> 4) * 8;
    const unsigned aHi0 = whiB + (unsigned)((lrow) * SW + kq * 128 + lk8) * 2;
    const unsigned aHi1 = whiB + (unsigned)((16 + lrow) * SW + kq * 128 + lk8) * 2;
    const unsigned aLo0 = wloB + (unsigned)((lrow) * SW + kq * 128 + lk8) * 2;
    const unsigned aLo1 = wloB + (unsigned)((16 + lrow) * SW + kq * 128 + lk8) * 2;

    // B lane offset (elements) into hbuf [b][k]
    const size_t lnoff = (size_t)(bb * 32 + ni * 8 + (lane >> 2)) * HID
                         + kq * 128 + (lane & 3) * 2;
    // partial store positions
    const int pr = lane >> 2;
    const int pc = ni * 8 + (lane & 3) * 2;
    float* pp = p_sm + kq * (32 * PS);

    for (int t = 0; t < TS; t++) {
        const __nv_bfloat16* pbh = g_hbHi[t & 1] + lnoff;
        const __nv_bfloat16* pbl = g_hbLo[t & 1] + lnoff;

        float d0[4] = {0.f, 0.f, 0.f, 0.f};
        float d1[4] = {0.f, 0.f, 0.f, 0.f};
#pragma unroll
        for (int s = 0; s < 8; s++) {
            unsigned ah0[4], ah1[4], al0[4], al1[4];
            ldmat4(ah0, aHi0 + s * 32);
            ldmat4(ah1, aHi1 + s * 32);
            ldmat4(al0, aLo0 + s * 32);
            ldmat4(al1, aLo1 + s * 32);
            unsigned bh[2], bl[2];
            bh[0] = ldcg_u32(pbh + s * 16);
            bh[1] = ldcg_u32(pbh + s * 16 + 8);
            bl[0] = ldcg_u32(pbl + s * 16);
            bl[1] = ldcg_u32(pbl + s * 16 + 8);
            mma16816(d0, ah0, bh);
            mma16816(d0, ah0, bl);
            mma16816(d0, al0, bh);
            mma16816(d1, ah1, bh);
            mma16816(d1, ah1, bl);
            mma16816(d1, al1, bh);
        }

        *(float2*)&pp[(pr + 0)  * PS + pc] = make_float2(d0[0], d0[1]);
        *(float2*)&pp[(pr + 8)  * PS + pc] = make_float2(d0[2], d0[3]);
        *(float2*)&pp[(pr + 16) * PS + pc] = make_float2(d1[0], d1[1]);
        *(float2*)&pp[(pr + 24) * PS + pc] = make_float2(d1[2], d1[3]);
        __syncthreads();

        if (tid < 256) {
            float r[4];
#pragma unroll
            for (int g = 0; g < 4; g++) {
                int m = g * 8 + cj;
                r[g] = p_sm[0 * (32 * PS) + m * PS + cb]
                     + p_sm[1 * (32 * PS) + m * PS + cb]
                     + p_sm[2 * (32 * PS) + m * PS + cb]
                     + p_sm[3 * (32 * PS) + m * PS + cb];
            }
            float ig = fsigmoid_(r[0] + vx0);
            float fg = fsigmoid_(r[1] + vx1);
            float gg = ftanh_(r[2] + vx2);
            float og = fsigmoid_(r[3] + vx3);
            c = fg * c + ig * gg;
            h = og * ftanh_(c);
            o_f32[cb * 9 + cj] = h;
            __nv_bfloat16 hh = __float2bfloat16(h);
            __nv_bfloat16 hl = __float2bfloat16(h - __bfloat162float(hh));
            ((__nv_bfloat16*)o_hi)[cb * 8 + cj] = hh;
            ((__nv_bfloat16*)o_lo)[cb * 8 + cj] = hl;
        }
        __syncthreads();

        // coalesced hbuf publish (tid<128): 32 b x 16B per array
        if (tid < 128) {
            int b = tid >> 2, w = tid & 3;
            size_t dst = (size_t)(bb * 32 + b) * HID + jb * 8;
            ((unsigned*)(g_hbHi[(t + 1) & 1] + dst))[w] = o_hi[b * 4 + w];
            ((unsigned*)(g_hbLo[(t + 1) & 1] + dst))[w] = o_lo[b * 4 + w];
        }
        __syncthreads();
        if (tid == 0) {
            red_release_add(bar, 1u);
            expect += NGRP;
        }

        // overlap with spin: out store + next-step xg prefetch
        if (tid < 128) {
            int b = tid >> 2, q = tid & 3;
            size_t orow = ((size_t)t * BS + bb * 32 + b) * HID + jb * 8;
            out[orow + q]     = o_f32[b * 9 + q];
            out[orow + q + 4] = o_f32[b * 9 + q + 4];
        }
        if (tid < 256 && t + 1 < TS) {
            int toff = (t + 1) * BS;
            vx0 = __ldg(xp0 + toff);
            vx1 = __ldg(xp1 + toff);
            vx2 = __ldg(xp2 + toff);
            vx3 = __ldg(xp3 + toff);
        }
        if (tid == 0) {
            while (ld_acquire(bar) < expect) { }
        }
        __syncthreads();
    }

    if (tid < 256) {
        hn[(size_t)bg * HID + jg] = h;
        cn[(size_t)bg * HID + jg] = c;
    }
}

// ---------------- launch ----------------------------------------------------
extern "C" void kernel_launch(void* const* d_in, const int* in_sizes, int n_in,
                              void* d_out, int out_size)
{
    const float* x    = (const float*)d_in[0];
    const float* h0   = (const float*)d_in[1];
    const float* c0   = (const float*)d_in[2];
    const float* W_ih = (const float*)d_in[3];
    const float* W_hh = (const float*)d_in[4];
    const float* b_ih = (const float*)d_in[5];
    const float* b_hh = (const float*)d_in[6];
    float* out = (float*)d_out;

    cudaFuncSetAttribute(lstm_kernel, cudaFuncAttributeMaxDynamicSharedMemorySize, LSTM_SMEM);
    cudaFuncSetAttribute(gemm_mma, cudaFuncAttributeMaxDynamicSharedMemorySize, GSMEM);

    void* pv;
    cudaGetSymbolAddress(&pv, g_out1);  float* p_out1 = (float*)pv;
    cudaGetSymbolAddress(&pv, g_xgates); const float* p_xg = (const float*)pv;
    cudaGetSymbolAddress(&pv, g_whi);   __nv_bfloat16* p_whi = (__nv_bfloat16*)pv;
    cudaGetSymbolAddress(&pv, g_wlo);   __nv_bfloat16* p_wlo = (__nv_bfloat16*)pv;
    cudaGetSymbolAddress(&pv, g_rwhi);  __nv_bfloat16* p_rwhi = (__nv_bfloat16*)pv;
    cudaGetSymbolAddress(&pv, g_rwlo);  __nv_bfloat16* p_rwlo = (__nv_bfloat16*)pv;

    dim3 ggrid(G4 / 128, MROWS / 128);   // (16, 512)

    // Layer 0
    convert_split<<<256, 256>>>(W_ih, p_whi, p_wlo, (size_t)G4 * HID, 0);
    convert_split<<<256, 256>>>(W_hh, p_rwhi, p_rwlo, (size_t)G4 * HID, 1);
    gemm_mma<<<ggrid, 512, GSMEM>>>(x, p_whi, p_wlo, b_ih, b_hh);
    lstm_kernel<<<NCTA, LTHREADS, LSTM_SMEM>>>(
        p_rwhi, p_rwlo, h0, c0, p_xg, p_out1,
        out + TBH, out + TBH + 2 * (size_t)BH);

    // Layer 1
    convert_split<<<256, 256>>>(W_ih + (size_t)G4 * HID, p_whi, p_wlo, (size_t)G4 * HID, 0);
    convert_split<<<256, 256>>>(W_hh + (size_t)G4 * HID, p_rwhi, p_rwlo, (size_t)G4 * HID, 1);
    gemm_mma<<<ggrid, 512, GSMEM>>>(p_out1, p_whi, p_wlo, b_ih + G4, b_hh + G4);
    lstm_kernel<<<NCTA, LTHREADS, LSTM_SMEM>>>(
        p_rwhi, p_rwlo, h0 + BH, c0 + BH, p_xg, out,
        out + TBH + (size_t)BH, out + TBH + 3 * (size_t)BH);

    (void)in_sizes; (void)n_in; (void)out_size;
}